// round 4
// baseline (speedup 1.0000x reference)
#include <cuda_runtime.h>
#include <cuda_bf16.h>
#include <math.h>

#define UNITS   256
#define FT_DIM  128
#define BATCH   32
#define TSTEPS  2048
#define EPSILON 0.01f
#define GAMMA   0.01f

// ---------------------------------------------------------------------------
// Device scratch (allocation-free contract: __device__ globals)
// ---------------------------------------------------------------------------
// Packed bf16x2 off-diagonal M, layout: Mpack[u*128 + i] = ( M[2i][u], M[2i+1][u] )
// with the diagonal zeroed (handled in fp32 in the scan).
__device__ unsigned g_Mpack[UNITS * (UNITS / 2)];
// h = x@V + bias, fp32, layout [B, T, U]
__device__ float g_h[(size_t)BATCH * TSTEPS * UNITS];

// ---------------------------------------------------------------------------
// Helpers
// ---------------------------------------------------------------------------
__device__ __forceinline__ __nv_bfloat162 u2b(unsigned x) {
    return *reinterpret_cast<__nv_bfloat162*>(&x);
}

// ---------------------------------------------------------------------------
// Kernel 1: build packed bf16 M = W - W^T (diag -> 0)
// ---------------------------------------------------------------------------
__global__ void prep_M_kernel(const float* __restrict__ W) {
    int id = blockIdx.x * blockDim.x + threadIdx.x;      // 0 .. 32767
    int u = id >> 7;        // column (unit owned by scan thread u)
    int i = id & 127;       // pair index
    int k0 = 2 * i;
    int k1 = 2 * i + 1;
    float m0 = (k0 == u) ? 0.0f : (W[k0 * UNITS + u] - W[u * UNITS + k0]);
    float m1 = (k1 == u) ? 0.0f : (W[k1 * UNITS + u] - W[u * UNITS + k1]);
    __nv_bfloat162 p = __floats2bfloat162_rn(m0, m1);    // low = m0, high = m1
    g_Mpack[id] = *reinterpret_cast<unsigned*>(&p);
}

// ---------------------------------------------------------------------------
// Kernel 2: fp32 GEMM  h[R, 256] = x[R, 128] @ V[128, 256] + bias
// R = B*T = 65536.  Tile 64x64, BK=32, 256 threads, 4x4 microtile.
// ---------------------------------------------------------------------------
#define BM 64
#define BN 64
#define BK 32

__global__ void __launch_bounds__(256) gemm_h_kernel(
    const float* __restrict__ x,
    const float* __restrict__ V,
    const float* __restrict__ bias)
{
    __shared__ float As[BK][BM + 1];   // [k][m], +1 pad: conflict-free stores
    __shared__ float Bs[BK][BN];       // [k][n]

    const int tid = threadIdx.x;
    const int rowBase = blockIdx.x * BM;
    const int colBase = blockIdx.y * BN;
    const int ty = tid >> 4;           // 0..15
    const int tx = tid & 15;           // 0..15

    float acc[4][4];
#pragma unroll
    for (int i = 0; i < 4; i++)
#pragma unroll
        for (int j = 0; j < 4; j++) acc[i][j] = 0.0f;

    for (int k0 = 0; k0 < FT_DIM; k0 += BK) {
        // Load A tile (64x32) -> As[k][m], coalesced on k
#pragma unroll
        for (int i = 0; i < 8; i++) {
            int idx = tid + i * 256;           // 0..2047
            int m = idx >> 5;
            int k = idx & 31;
            As[k][m] = __ldg(&x[(size_t)(rowBase + m) * FT_DIM + k0 + k]);
        }
        // Load B tile (32x64) -> Bs[k][n], coalesced on n
#pragma unroll
        for (int i = 0; i < 8; i++) {
            int idx = tid + i * 256;
            int k = idx >> 6;
            int n = idx & 63;
            Bs[k][n] = __ldg(&V[(size_t)(k0 + k) * UNITS + colBase + n]);
        }
        __syncthreads();

#pragma unroll
        for (int k = 0; k < BK; k++) {
            float a0 = As[k][ty * 4 + 0];
            float a1 = As[k][ty * 4 + 1];
            float a2 = As[k][ty * 4 + 2];
            float a3 = As[k][ty * 4 + 3];
            float4 bv = *reinterpret_cast<const float4*>(&Bs[k][tx * 4]);
            acc[0][0] = fmaf(a0, bv.x, acc[0][0]);
            acc[0][1] = fmaf(a0, bv.y, acc[0][1]);
            acc[0][2] = fmaf(a0, bv.z, acc[0][2]);
            acc[0][3] = fmaf(a0, bv.w, acc[0][3]);
            acc[1][0] = fmaf(a1, bv.x, acc[1][0]);
            acc[1][1] = fmaf(a1, bv.y, acc[1][1]);
            acc[1][2] = fmaf(a1, bv.z, acc[1][2]);
            acc[1][3] = fmaf(a1, bv.w, acc[1][3]);
            acc[2][0] = fmaf(a2, bv.x, acc[2][0]);
            acc[2][1] = fmaf(a2, bv.y, acc[2][1]);
            acc[2][2] = fmaf(a2, bv.z, acc[2][2]);
            acc[2][3] = fmaf(a2, bv.w, acc[2][3]);
            acc[3][0] = fmaf(a3, bv.x, acc[3][0]);
            acc[3][1] = fmaf(a3, bv.y, acc[3][1]);
            acc[3][2] = fmaf(a3, bv.z, acc[3][2]);
            acc[3][3] = fmaf(a3, bv.w, acc[3][3]);
        }
        __syncthreads();
    }

    // Store with bias
    float b0 = bias[colBase + tx * 4 + 0];
    float b1 = bias[colBase + tx * 4 + 1];
    float b2 = bias[colBase + tx * 4 + 2];
    float b3 = bias[colBase + tx * 4 + 3];
#pragma unroll
    for (int i = 0; i < 4; i++) {
        size_t row = (size_t)(rowBase + ty * 4 + i);
        float4 v;
        v.x = acc[i][0] + b0;
        v.y = acc[i][1] + b1;
        v.z = acc[i][2] + b2;
        v.w = acc[i][3] + b3;
        *reinterpret_cast<float4*>(&g_h[row * UNITS + colBase + tx * 4]) = v;
    }
}

// ---------------------------------------------------------------------------
// Kernel 3: the sequential scan. One CTA per batch (32 CTAs, 256 threads).
// Thread u owns state s_u (fp32) and M column u (128 bf16x2 registers).
// Per step: z_u = h[t][u] - GAMMA*s_u + sum_k s_k * Moff[k][u]   (bf16 dot)
//           s_u += EPS * tanh(z_u)
// State is shared via double-buffered bf16x2 smem (1 bar.sync / step).
// ---------------------------------------------------------------------------
__global__ void __launch_bounds__(256, 1) scan_kernel(
    const float* __restrict__ x0,
    float* __restrict__ out)
{
    __shared__ __align__(16) unsigned sbuf[2][UNITS / 2];

    const int u = threadIdx.x;
    const int b = blockIdx.x;

    // Load M column u into registers (one-time, vectorized)
    unsigned mreg[128];
    {
        const uint4* mp = reinterpret_cast<const uint4*>(g_Mpack + u * 128);
#pragma unroll
        for (int i = 0; i < 32; i++) {
            uint4 v = mp[i];
            mreg[4 * i + 0] = v.x;
            mreg[4 * i + 1] = v.y;
            mreg[4 * i + 2] = v.z;
            mreg[4 * i + 3] = v.w;
        }
    }

    float s = x0[u];

    // Seed shared state buffer 0
    {
        __nv_bfloat16* p = reinterpret_cast<__nv_bfloat16*>(sbuf[0]);
        p[u] = __float2bfloat16(s);
    }
    __syncthreads();

    const float* hb = g_h + (size_t)b * TSTEPS * UNITS + u;
    float* ob = out + (size_t)b * TSTEPS * UNITS + u;

    // h prefetch queue (distance 2): the h load never sits on the
    // inter-step critical path.
    float h0 = hb[0];
    float h1 = hb[UNITS];

    int cur = 0;
    for (int t = 0; t < TSTEPS; t++) {
        float hc = h0;
        h0 = h1;
        if (t + 2 < TSTEPS) h1 = hb[(size_t)(t + 2) * UNITS];

        // bf16x2 dot product: 128 HFMA2, 4 independent accumulator chains
        __nv_bfloat162 a0 = __float2bfloat162_rn(0.0f);
        __nv_bfloat162 a1 = __float2bfloat162_rn(0.0f);
        __nv_bfloat162 a2 = __float2bfloat162_rn(0.0f);
        __nv_bfloat162 a3 = __float2bfloat162_rn(0.0f);

        const uint4* sv = reinterpret_cast<const uint4*>(sbuf[cur]);
#pragma unroll
        for (int i = 0; i < 32; i++) {
            uint4 v = sv[i];   // uniform-address LDS.128: broadcast, conflict-free
            a0 = __hfma2(u2b(mreg[4 * i + 0]), u2b(v.x), a0);
            a1 = __hfma2(u2b(mreg[4 * i + 1]), u2b(v.y), a1);
            a2 = __hfma2(u2b(mreg[4 * i + 2]), u2b(v.z), a2);
            a3 = __hfma2(u2b(mreg[4 * i + 3]), u2b(v.w), a3);
        }

        float2 f0 = __bfloat1622float2(a0);
        float2 f1 = __bfloat1622float2(a1);
        float2 f2 = __bfloat1622float2(a2);
        float2 f3 = __bfloat1622float2(a3);
        float dot = ((f0.x + f0.y) + (f1.x + f1.y)) + ((f2.x + f2.y) + (f3.x + f3.y));

        float z = hc + dot - GAMMA * s;      // exact fp32 diagonal term
        s += EPSILON * tanhf(z);

        // Publish new state FIRST (critical path: other threads wait on it),
        // then the off-path global store.
        reinterpret_cast<__nv_bfloat16*>(sbuf[cur ^ 1])[u] = __float2bfloat16(s);
        ob[(size_t)t * UNITS] = s;           // coalesced STG, not on critical path
        cur ^= 1;
        __syncthreads();
    }
}

// ---------------------------------------------------------------------------
// Launch: inputs per metadata order: x, V, W, bias, x0
// ---------------------------------------------------------------------------
extern "C" void kernel_launch(void* const* d_in, const int* in_sizes, int n_in,
                              void* d_out, int out_size)
{
    const float* x    = (const float*)d_in[0];   // [32, 2048, 128]
    const float* V    = (const float*)d_in[1];   // [128, 256]
    const float* W    = (const float*)d_in[2];   // [256, 256]
    const float* bias = (const float*)d_in[3];   // [256]
    const float* x0   = (const float*)d_in[4];   // [256]
    float* out = (float*)d_out;                  // [32, 2048, 256]

    (void)in_sizes; (void)n_in; (void)out_size;

    // 1) Pack M = W - W^T (off-diagonal, bf16x2)
    prep_M_kernel<<<(UNITS * UNITS / 2) / 256, 256>>>(W);

    // 2) h = x @ V + bias (fp32 GEMM)
    dim3 ggrid((BATCH * TSTEPS) / BM, UNITS / BN);
    gemm_h_kernel<<<ggrid, 256>>>(x, V, bias);

    // 3) Sequential scan, one CTA per batch
    scan_kernel<<<BATCH, 256>>>(x0, out);
}